// round 13
// baseline (speedup 1.0000x reference)
#include <cuda_runtime.h>
#include <cstdint>
#include <math.h>

#define FULLM 0xFFFFFFFFu
#define TPB   256
#define WPB   (TPB / 32)           // 8 warps per block
#define TROWS 24                   // rows per tile (geo: exactly 2 batches)
#define WTILE 3168                 // bytes per tile buffer (24*132)
#define NBUF  3                    // ring depth -> 2 tiles always in flight
#define WSLICE (NBUF * WTILE)      // 9504 B per warp
#define GRID  444                  // 3 blocks/SM * 148 SMs (smem 3*76KB)

struct ContTab { float v[13]; };

__constant__ float CW_C[12] = {1.0f, 0.8f, 0.64f, 0.512f, 0.4096f, 0.32768f,
                               0.262144f, 0.2097152f, 0.16777216f, 0.134217728f,
                               0.1073741824f, 0.08589934592f};

// 0=mask_ce_sum 1=valid_cnt 2=correct_sum 3=error_sum 4=prefix_sum
__device__ double   g_acc[5];
__device__ unsigned g_done;

__device__ __forceinline__ double warp_dsum(double v) {
    #pragma unroll
    for (int d = 16; d; d >>= 1) v += __shfl_xor_sync(FULLM, v, d);
    return v;
}

__device__ __forceinline__ void cp_async16(unsigned int s, const void* g) {
    asm volatile("cp.async.cg.shared.global [%0], [%1], 16;\n" :: "r"(s), "l"(g));
}
__device__ __forceinline__ void cp_async4(unsigned int s, const void* g) {
    asm volatile("cp.async.ca.shared.global [%0], [%1], 4;\n" :: "r"(s), "l"(g));
}
__device__ __forceinline__ void cp_commit()   { asm volatile("cp.async.commit_group;\n"); }
__device__ __forceinline__ void cp_wait2()    { asm volatile("cp.async.wait_group 2;\n"); }
__device__ __forceinline__ void cp_wait_all() { asm volatile("cp.async.wait_group 0;\n"); }

__global__ __launch_bounds__(TPB, 3) void fused_kernel(
    const float* __restrict__ geo, const int* __restrict__ pos,
    const float* __restrict__ mgo, const int* __restrict__ gt,
    const float* __restrict__ aux, const float* __restrict__ tok,
    const float* __restrict__ sigma, float* __restrict__ out,
    int B, int nrows, int NTg, int NT,
    int lastGeoNb, int lastMaskNr, ContTab cont)
{
    // Per-warp private 3-deep ring; no block barriers in the main loop.
    // Every tile (geo or mask) is 3168 B -> one unified fast copy path.
    // int32 indexing throughout (all offsets < 2^31).
    extern __shared__ char shm[];
    __shared__ double shred[WPB * 5];

    const int tid  = threadIdx.x;
    const int lane = tid & 31;
    const int w    = tid >> 5;
    const unsigned int dst0 =
        (unsigned int)__cvta_generic_to_shared(shm) + w * WSLICE;
    const float* buf0 = (const float*)(shm + w * WSLICE);

    // Geo: lane l (l<24) owns row l; j = l%12, batch = l/12. Row stride 132 B
    // -> smem bank of elem i for lane l is (l+i)%32: conflict-free.
    const int  jj    = (lane < 12) ? lane : lane - 12;
    const int  batch = (lane < 12) ? 0 : 1;
    const float cwj  = CW_C[jj];
    const float cwj1 = cwj + 1.0f;

    float accS = 0.f, accV = 0.f, accC = 0.f, accE = 0.f, accP = 0.f;

    // Issue cp.asyncs for tile u into ring slot. Fast path: 198 16B-chunks
    // (3168 B) for BOTH tile kinds. Exactly one commit_group per call.
    auto load_tile = [&](int u, int slot) {
        const unsigned int dst = dst0 + slot * WTILE;
        const bool raggedGeo  = (u == NTg - 1) && (lastGeoNb != 2);
        const bool raggedMask = (u == NT - 1) && (lastMaskNr != TROWS);
        const char* src = (u < NTg)
            ? (const char*)geo + u * WTILE
            : (const char*)mgo + (u - NTg) * WTILE;
        if (u < NTg ? !raggedGeo : !raggedMask) {
            #pragma unroll
            for (int k = 0; k < 6; k++)
                cp_async16(dst + (lane + k * 32) * 16, src + (lane + k * 32) * 16);
            if (lane < 6)
                cp_async16(dst + (lane + 192) * 16, src + (lane + 192) * 16);
        } else {
            const int bytes = (u < NTg) ? lastGeoNb * 1584 : lastMaskNr * 132;
            const int n16 = bytes >> 4;
            for (int c = lane; c < n16; c += 32)
                cp_async16(dst + c * 16, src + c * 16);
            for (int c = (n16 << 2) + lane; c < (bytes >> 2); c += 32)
                cp_async4(dst + c * 4, src + c * 4);
        }
        cp_commit();
    };

    const int gw = blockIdx.x * WPB + w;           // global warp id
    const int nw = GRID * WPB;                     // total warps

    if (gw < NT)      load_tile(gw, 0);      else cp_commit();
    if (gw + nw < NT) load_tile(gw + nw, 1); else cp_commit();

    int cur = 0;
    for (int u = gw; u < NT; u += nw) {
        // Prefetch distance 2 into the slot last read two iters ago.
        const int un = u + 2 * nw;
        int slot2 = cur + 2; if (slot2 >= NBUF) slot2 -= NBUF;
        if (un < NT) load_tile(un, slot2);
        else         cp_commit();              // uniform group counts

        // Hoisted index/target load for tile u (hides under the group wait).
        int pre = -100;
        int nb = 2, nr = TROWS;
        if (u < NTg) {
            if (u == NTg - 1) nb = lastGeoNb;
            if (lane < nb * 12) pre = pos[u * 26 + batch * 13 + jj + 1];
        } else {
            if (u == NT - 1) nr = lastMaskNr;
            if (lane < nr) pre = gt[(u - NTg) * TROWS + lane];
        }

        cp_wait2();                            // group(u) complete; 2 in flight
        __syncwarp();                          // all lanes' chunks visible

        const float* buf = buf0 + cur * (WTILE / 4);
        if (u < NTg) {
            // ---------- geo tile: 2 batches x 12 positions ----------
            const bool act = lane < nb * 12;
            float cel = 0.f;
            bool  cor = false;
            if (act) {
                const float* p = buf + lane * 33;
                float m0 = -1e30f, m1 = -1e30f, m2 = -1e30f, m3 = -1e30f;
                float s0 = 0.f, s1 = 0.f, s2 = 0.f, s3 = 0.f;
                #pragma unroll
                for (int i = 0; i < 32; i += 4) {
                    float a = p[i], b = p[i+1], c = p[i+2], d = p[i+3];
                    m0 = fmaxf(m0, a); m1 = fmaxf(m1, b);
                    m2 = fmaxf(m2, c); m3 = fmaxf(m3, d);
                    s0 += __expf(a); s1 += __expf(b);
                    s2 += __expf(c); s3 += __expf(d);
                }
                const float e32 = p[32];
                const float m = fmaxf(fmaxf(fmaxf(m0, m1), fmaxf(m2, m3)), e32);
                const float s = (s0 + s1) + (s2 + s3) + __expf(e32);
                const float pt = p[pre];       // pre in 0..32 when act
                cor = (pt == m);  // ties measure-zero for random logits
                cel = (pre == 32) ? 0.f : (__logf(s) - pt);
            }
            const unsigned bal = __ballot_sync(FULLM, cor);
            if (act) {
                const unsigned m12 = (bal >> (batch * 12)) & 0xFFFu;
                const int mi = (m12 == 0xFFFu) ? 0 : (__ffs((int)~m12) - 1);
                const bool ok = (m12 >> jj) & 1u;
                accC += ok ? cel * cwj  : 0.f;
                accE += ok ? 0.f        : cel * cwj1;
                accP += (jj < mi) ? cel * cont.v[mi] : 0.f;
            }
        } else {
            // ---------- mask tile: TROWS rows of 33 ----------
            if (lane < nr) {
                const float* p = buf + lane * 33;
                float s0 = 0.f, s1 = 0.f, s2 = 0.f, s3 = 0.f;
                #pragma unroll
                for (int i = 0; i < 32; i += 4) {
                    s0 += __expf(p[i]);   s1 += __expf(p[i+1]);
                    s2 += __expf(p[i+2]); s3 += __expf(p[i+3]);
                }
                const float s = (s0 + s1) + (s2 + s3) + __expf(p[32]);
                if (pre != -100) {
                    const int tc = min(max(pre, 0), 32);
                    accS += __logf(s) - p[tc];
                    accV += 1.f;
                }
            }
        }
        __syncwarp();      // all lanes done reading buf before ring reuse
        cur += 1; if (cur >= NBUF) cur -= NBUF;
    }
    cp_wait_all();         // drain in-flight groups

    // ---------------- block reduction -> global atomics ----------------
    double d0 = warp_dsum((double)accS);
    double d1 = warp_dsum((double)accV);
    double d2 = warp_dsum((double)accC);
    double d3 = warp_dsum((double)accE);
    double d4 = warp_dsum((double)accP);
    if (lane == 0) {
        shred[w] = d0; shred[WPB + w] = d1; shred[2*WPB + w] = d2;
        shred[3*WPB + w] = d3; shred[4*WPB + w] = d4;
    }
    __syncthreads();
    if (tid == 0) {
        double a0 = 0, a1 = 0, a2 = 0, a3 = 0, a4 = 0;
        #pragma unroll
        for (int i = 0; i < WPB; i++) {
            a0 += shred[i];          a1 += shred[WPB + i];
            a2 += shred[2*WPB + i];  a3 += shred[3*WPB + i];
            a4 += shred[4*WPB + i];
        }
        atomicAdd(&g_acc[0], a0);
        atomicAdd(&g_acc[1], a1);
        atomicAdd(&g_acc[2], a2);
        atomicAdd(&g_acc[3], a3);
        atomicAdd(&g_acc[4], a4);
        __threadfence();
        unsigned done = atomicAdd(&g_done, 1u);
        if (done == gridDim.x - 1) {
            // last block: read-and-zero (deterministic across graph replays)
            double s0 = __longlong_as_double(atomicExch((unsigned long long*)&g_acc[0], 0ull));
            double s1 = __longlong_as_double(atomicExch((unsigned long long*)&g_acc[1], 0ull));
            double s2 = __longlong_as_double(atomicExch((unsigned long long*)&g_acc[2], 0ull));
            double s3 = __longlong_as_double(atomicExch((unsigned long long*)&g_acc[3], 0ull));
            double s4 = __longlong_as_double(atomicExch((unsigned long long*)&g_acc[4], 0ull));
            atomicExch(&g_done, 0u);

            const double den = (double)B * 12.0;
            double mask_loss = s0 / fmax(s1, 1.0);
            double pl = s4 / den, cl = s2 / den, el = s3 / den;
            double gl = pl + cl + el;
            double L[4] = { gl, mask_loss, (double)aux[0], (double)tok[0] };
            double wsum = 0.0, prod = 1.0;
            #pragma unroll
            for (int i = 0; i < 4; i++) {
                double sg = (double)sigma[i];
                wsum += 0.5 * L[i] / (sg * sg);
                prod *= sg;
            }
            wsum += log(prod);
            out[0] = (float)wsum;
            out[1] = (float)pl;
            out[2] = (float)cl;
            out[3] = (float)el;
            out[4] = (float)mask_loss;
        }
    }
}

extern "C" void kernel_launch(void* const* d_in, const int* in_sizes, int n_in,
                              void* d_out, int out_size) {
    (void)n_in; (void)out_size;
    const float* geo   = (const float*)d_in[0];   // (B, 12, 33) f32
    const float* mgo   = (const float*)d_in[1];   // (B, 13, 33) f32
    const int*   pos   = (const int*)  d_in[2];   // (B, 13) i32
    const int*   gt    = (const int*)  d_in[3];   // (B, 13) i32
    const float* aux   = (const float*)d_in[4];
    const float* tok   = (const float*)d_in[5];
    const float* sigma = (const float*)d_in[6];
    float* out = (float*)d_out;

    const int B     = (int)((long)in_sizes[0] / 396);
    const int nrows = (int)((long)in_sizes[1] / 33);  // B * 13
    const int NTg   = (B + 1) / 2;                    // geo tiles (2 batches)
    const int NTm   = (nrows + TROWS - 1) / TROWS;    // mask tiles (24 rows)
    const int NT    = NTg + NTm;
    const int lastGeoNb  = B - (NTg - 1) * 2;         // 1 or 2
    const int lastMaskNr = nrows - (NTm - 1) * TROWS; // 1..24

    // CONT_REWARDS closed-form geometric series == reference's Riemann sum
    ContTab cont;
    cont.v[0] = 0.0f;
    for (int k = 1; k <= 12; k++) {
        double b = (double)k;
        double r = pow(0.8, b / 1999.0);
        double integral = (b / 2000.0) * (1.0 - pow(r, 2000.0)) / (1.0 - r);
        cont.v[k] = (float)(1.0 / integral);
    }

    const int dyn_smem = WPB * WSLICE;            // 8 warps * 9504 B = 76032 B
    cudaFuncSetAttribute(fused_kernel,
                         cudaFuncAttributeMaxDynamicSharedMemorySize, dyn_smem);
    fused_kernel<<<GRID, TPB, dyn_smem>>>(geo, pos, mgo, gt, aux, tok, sigma, out,
                                          B, nrows, NTg, NT,
                                          lastGeoNb, lastMaskNr, cont);
}

// round 14
// speedup vs baseline: 1.3574x; 1.3574x over previous
#include <cuda_runtime.h>
#include <cstdint>
#include <math.h>

#define FULLM 0xFFFFFFFFu
#define TPB   256
#define WPB   (TPB / 32)           // 8 warps per block
#define WTILE 4224                 // bytes per warp tile (32 rows * 132 B)
#define NBUF  2
#define WSLICE (NBUF * WTILE)      // 8448 B per warp
#define GRID  444                  // 3 blocks/SM * 148 SMs (smem 3*67.6KB=203KB)

struct ContTab { float v[13]; };

// CORRECT_W = 0.8^j
__constant__ float CW_C[12] = {1.0f, 0.8f, 0.64f, 0.512f, 0.4096f, 0.32768f,
                               0.262144f, 0.2097152f, 0.16777216f, 0.134217728f,
                               0.1073741824f, 0.08589934592f};

// 0=mask_ce_sum 1=valid_cnt 2=correct_sum 3=error_sum 4=prefix_sum
__device__ double   g_acc[5];
__device__ unsigned g_done;

__device__ __forceinline__ double warp_dsum(double v) {
    #pragma unroll
    for (int d = 16; d; d >>= 1) v += __shfl_xor_sync(FULLM, v, d);
    return v;
}

// .L2::256B: each 16B request prefetches a 256B line into L2 -> DRAM sees
// line-granular reads; sibling requests hit L2. Pure hint, no semantics change.
__device__ __forceinline__ void cp_async16(unsigned int s, const void* g) {
    asm volatile("cp.async.cg.shared.global.L2::256B [%0], [%1], 16;\n" :: "r"(s), "l"(g));
}
__device__ __forceinline__ void cp_async4(unsigned int s, const void* g) {
    asm volatile("cp.async.ca.shared.global [%0], [%1], 4;\n" :: "r"(s), "l"(g));
}
__device__ __forceinline__ void cp_commit()   { asm volatile("cp.async.commit_group;\n"); }
__device__ __forceinline__ void cp_wait1()    { asm volatile("cp.async.wait_group 1;\n"); }
__device__ __forceinline__ void cp_wait_all() { asm volatile("cp.async.wait_group 0;\n"); }

__global__ __launch_bounds__(TPB, 3) void fused_kernel(
    const float* __restrict__ geo, const int* __restrict__ pos,
    const float* __restrict__ mgo, const int* __restrict__ gt,
    const float* __restrict__ aux, const float* __restrict__ tok,
    const float* __restrict__ sigma, float* __restrict__ out,
    int B, long nrows, long NTg, long NT, ContTab cont)
{
    // Per-warp private double-buffered slices; NO block barriers in the main
    // loop — each warp is an independent load/compute pipeline (24 / SM).
    extern __shared__ char shm[];
    __shared__ double shred[WPB * 5];

    const int tid  = threadIdx.x;
    const int lane = tid & 31;
    const int w    = tid >> 5;
    const unsigned int slice =
        (unsigned int)__cvta_generic_to_shared(shm) + w * WSLICE;

    // Geo: lane l (l<24) owns row l of a 2-batch tile; j = l%12, batch = l/12.
    // Row stride 132 B -> smem bank of elem i for lane l is (l+i)%32: conflict-free.
    const int  jj    = (lane < 12) ? lane : lane - 12;
    const int  batch = (lane < 12) ? 0 : 1;
    const float cwj  = CW_C[jj];
    const float cwj1 = cwj + 1.0f;

    float accS = 0.f, accV = 0.f, accC = 0.f, accE = 0.f, accP = 0.f;

    // Issue all cp.asyncs for tile u into buffer bufidx (all 32 lanes help;
    // every call commits exactly one group -> uniform group counts).
    auto load_tile = [&](long u, int bufidx) {
        const unsigned int dst = slice + bufidx * WTILE;
        const char* src;
        int bytes;
        if (u < NTg) {
            const long b0 = u * 2;
            const int  nb = (int)min(2L, (long)B - b0);
            src   = (const char*)(geo + b0 * 396);
            bytes = nb * 1584;                        // 1584 % 16 == 0
        } else {
            const long r0 = (u - NTg) * 32;
            const int  nr = (int)min(32L, nrows - r0);
            src   = (const char*)(mgo + r0 * 33);
            bytes = nr * 132;
        }
        const int n16 = bytes >> 4;
        #pragma unroll
        for (int k = 0; k < 9; k++) {
            const int c = lane + k * 32;
            if (c < n16) cp_async16(dst + c * 16, src + (size_t)c * 16);
        }
        for (int c = (n16 << 2) + lane; c < (bytes >> 2); c += 32)  // tail
            cp_async4(dst + c * 4, src + (size_t)c * 4);
        cp_commit();
    };

    const long gw = (long)blockIdx.x * WPB + w;      // global warp id
    const long nw = (long)gridDim.x * WPB;           // total warps

    if (gw < NT) load_tile(gw, 0);
    else         cp_commit();                        // keep group counts uniform

    int cur = 0;
    for (long u = gw; u < NT; u += nw) {
        const long un = u + nw;
        if (un < NT) load_tile(un, cur ^ 1);
        else         cp_commit();

        // Hoisted index/target loads for tile u: issued BEFORE the group wait
        // so their latency hides under it (depend only on u, not smem).
        int  pre = -100;
        int  nb = 0, nr = 0;
        long b0 = 0, r0 = 0;
        if (u < NTg) {
            b0 = u * 2;
            nb = (int)min(2L, (long)B - b0);
            if (lane < nb * 12) pre = pos[(b0 + batch) * 13 + jj + 1];
        } else {
            r0 = (u - NTg) * 32;
            nr = (int)min(32L, nrows - r0);
            if (lane < nr) pre = gt[r0 + lane];
        }

        cp_wait1();                                  // own tile-u chunks done
        __syncwarp();                                // all lanes' chunks done

        const float* buf = (const float*)(shm + (size_t)w * WSLICE
                                              + (size_t)cur * WTILE);
        if (u < NTg) {
            // ------------- geo tile: 2 batches x 12 positions -------------
            const bool act = lane < nb * 12;
            float cel = 0.f;
            bool  cor = false;
            if (act) {
                const float* p = buf + lane * 33;
                float m0 = -1e30f, m1 = -1e30f, m2 = -1e30f, m3 = -1e30f;
                float s0 = 0.f, s1 = 0.f, s2 = 0.f, s3 = 0.f;
                #pragma unroll
                for (int i = 0; i < 32; i += 4) {
                    float a = p[i], b = p[i+1], c = p[i+2], d = p[i+3];
                    m0 = fmaxf(m0, a); m1 = fmaxf(m1, b);
                    m2 = fmaxf(m2, c); m3 = fmaxf(m3, d);
                    s0 += __expf(a); s1 += __expf(b);
                    s2 += __expf(c); s3 += __expf(d);
                }
                const float e32 = p[32];
                const float m = fmaxf(fmaxf(fmaxf(m0, m1), fmaxf(m2, m3)), e32);
                const float s = (s0 + s1) + (s2 + s3) + __expf(e32);
                const float pt = p[pre];             // pre in 0..32 when act
                cor = (pt == m);       // ties measure-zero for random logits
                cel = (pre == 32) ? 0.f : (__logf(s) - pt);
            }
            const unsigned bal = __ballot_sync(FULLM, cor);
            if (act) {
                const unsigned m12 = (bal >> (batch * 12)) & 0xFFFu;
                const int mi = (m12 == 0xFFFu) ? 0 : (__ffs((int)~m12) - 1);
                const bool ok = (m12 >> jj) & 1u;
                accC += ok ? cel * cwj  : 0.f;
                accE += ok ? 0.f        : cel * cwj1;
                accP += (jj < mi) ? cel * cont.v[mi] : 0.f;
            }
        } else {
            // ------------- mask tile: 32 rows of 33 -------------
            if (lane < nr) {
                const float* p = buf + lane * 33;
                float s0 = 0.f, s1 = 0.f, s2 = 0.f, s3 = 0.f;
                #pragma unroll
                for (int i = 0; i < 32; i += 4) {
                    s0 += __expf(p[i]);   s1 += __expf(p[i+1]);
                    s2 += __expf(p[i+2]); s3 += __expf(p[i+3]);
                }
                const float s = (s0 + s1) + (s2 + s3) + __expf(p[32]);
                const int tc = min(max(pre, 0), 32);
                if (pre != -100) {
                    accS += __logf(s) - p[tc];
                    accV += 1.f;
                }
            }
        }
        __syncwarp();       // all lanes done reading buf before it is refilled
        cur ^= 1;
    }
    cp_wait_all();          // drain in-flight groups before smem goes away

    // ---------------- block reduction -> global atomics ----------------
    double d0 = warp_dsum((double)accS);
    double d1 = warp_dsum((double)accV);
    double d2 = warp_dsum((double)accC);
    double d3 = warp_dsum((double)accE);
    double d4 = warp_dsum((double)accP);
    if (lane == 0) {
        shred[w] = d0; shred[WPB + w] = d1; shred[2*WPB + w] = d2;
        shred[3*WPB + w] = d3; shred[4*WPB + w] = d4;
    }
    __syncthreads();
    if (tid == 0) {
        double a0 = 0, a1 = 0, a2 = 0, a3 = 0, a4 = 0;
        #pragma unroll
        for (int i = 0; i < WPB; i++) {
            a0 += shred[i];          a1 += shred[WPB + i];
            a2 += shred[2*WPB + i];  a3 += shred[3*WPB + i];
            a4 += shred[4*WPB + i];
        }
        atomicAdd(&g_acc[0], a0);
        atomicAdd(&g_acc[1], a1);
        atomicAdd(&g_acc[2], a2);
        atomicAdd(&g_acc[3], a3);
        atomicAdd(&g_acc[4], a4);
        __threadfence();
        unsigned done = atomicAdd(&g_done, 1u);
        if (done == gridDim.x - 1) {
            // last block: read-and-zero (deterministic across graph replays)
            double s0 = __longlong_as_double(atomicExch((unsigned long long*)&g_acc[0], 0ull));
            double s1 = __longlong_as_double(atomicExch((unsigned long long*)&g_acc[1], 0ull));
            double s2 = __longlong_as_double(atomicExch((unsigned long long*)&g_acc[2], 0ull));
            double s3 = __longlong_as_double(atomicExch((unsigned long long*)&g_acc[3], 0ull));
            double s4 = __longlong_as_double(atomicExch((unsigned long long*)&g_acc[4], 0ull));
            atomicExch(&g_done, 0u);

            const double den = (double)B * 12.0;
            double mask_loss = s0 / fmax(s1, 1.0);
            double pl = s4 / den, cl = s2 / den, el = s3 / den;
            double gl = pl + cl + el;
            double L[4] = { gl, mask_loss, (double)aux[0], (double)tok[0] };
            double wsum = 0.0, prod = 1.0;
            #pragma unroll
            for (int i = 0; i < 4; i++) {
                double sg = (double)sigma[i];
                wsum += 0.5 * L[i] / (sg * sg);
                prod *= sg;
            }
            wsum += log(prod);
            out[0] = (float)wsum;
            out[1] = (float)pl;
            out[2] = (float)cl;
            out[3] = (float)el;
            out[4] = (float)mask_loss;
        }
    }
}

extern "C" void kernel_launch(void* const* d_in, const int* in_sizes, int n_in,
                              void* d_out, int out_size) {
    (void)n_in; (void)out_size;
    const float* geo   = (const float*)d_in[0];   // (B, 12, 33) f32
    const float* mgo   = (const float*)d_in[1];   // (B, 13, 33) f32
    const int*   pos   = (const int*)  d_in[2];   // (B, 13) i32
    const int*   gt    = (const int*)  d_in[3];   // (B, 13) i32
    const float* aux   = (const float*)d_in[4];
    const float* tok   = (const float*)d_in[5];
    const float* sigma = (const float*)d_in[6];
    float* out = (float*)d_out;

    const int  B     = (int)((long)in_sizes[0] / 396);
    const long nrows = (long)in_sizes[1] / 33;    // B * 13
    const long NTg   = ((long)B + 1) / 2;         // geo tiles (2 batches each)
    const long NTm   = (nrows + 31) / 32;         // mask tiles (32 rows each)
    const long NT    = NTg + NTm;

    // CONT_REWARDS closed-form geometric series == reference's Riemann sum
    ContTab cont;
    cont.v[0] = 0.0f;
    for (int k = 1; k <= 12; k++) {
        double b = (double)k;
        double r = pow(0.8, b / 1999.0);
        double integral = (b / 2000.0) * (1.0 - pow(r, 2000.0)) / (1.0 - r);
        cont.v[k] = (float)(1.0 / integral);
    }

    const int dyn_smem = WPB * WSLICE;            // 8 warps * 8448 B = 67584 B
    cudaFuncSetAttribute(fused_kernel,
                         cudaFuncAttributeMaxDynamicSharedMemorySize, dyn_smem);
    fused_kernel<<<GRID, TPB, dyn_smem>>>(geo, pos, mgo, gt, aux, tok, sigma, out,
                                          B, nrows, NTg, NT, cont);
}

// round 15
// speedup vs baseline: 1.4044x; 1.0346x over previous
#include <cuda_runtime.h>
#include <cstdint>
#include <math.h>

#define FULLM 0xFFFFFFFFu
#define TPB   256
#define WPB   (TPB / 32)           // 8 warps per block
#define WTILE 4224                 // bytes per warp tile (32 rows * 132 B)
#define NBUF  2
#define WSLICE (NBUF * WTILE)      // 8448 B per warp
#define GRID  444                  // 3 blocks/SM * 148 SMs

struct ContTab { float v[13]; };

__constant__ float CW_C[12] = {1.0f, 0.8f, 0.64f, 0.512f, 0.4096f, 0.32768f,
                               0.262144f, 0.2097152f, 0.16777216f, 0.134217728f,
                               0.1073741824f, 0.08589934592f};

// 0=mask_ce_sum 1=valid_cnt 2=correct_sum 3=error_sum 4=prefix_sum
__device__ double   g_acc[5];
__device__ unsigned g_done;

__device__ __forceinline__ double warp_dsum(double v) {
    #pragma unroll
    for (int d = 16; d; d >>= 1) v += __shfl_xor_sync(FULLM, v, d);
    return v;
}

__device__ __forceinline__ void mbar_init(unsigned int mbar) {
    asm volatile("mbarrier.init.shared.b64 [%0], 1;" :: "r"(mbar) : "memory");
}
__device__ __forceinline__ void mbar_expect_tx(unsigned int mbar, unsigned int bytes) {
    asm volatile("mbarrier.arrive.expect_tx.shared.b64 _, [%0], %1;"
                 :: "r"(mbar), "r"(bytes) : "memory");
}
__device__ __forceinline__ void bulk_g2s(unsigned int dst, const void* src,
                                         unsigned int bytes, unsigned int mbar) {
    asm volatile("cp.async.bulk.shared::cta.global.mbarrier::complete_tx::bytes "
                 "[%0], [%1], %2, [%3];"
                 :: "r"(dst), "l"(src), "r"(bytes), "r"(mbar) : "memory");
}
__device__ __forceinline__ void mbar_wait(unsigned int mbar, unsigned int parity) {
    asm volatile(
        "{\n\t.reg .pred P;\n\t"
        "W%=:\n\t"
        "mbarrier.try_wait.parity.acquire.cta.shared::cta.b64 P, [%0], %1, 0x989680;\n\t"
        "@P bra D%=;\n\t"
        "bra W%=;\n\t"
        "D%=:\n\t}"
        :: "r"(mbar), "r"(parity) : "memory");
}
__device__ __forceinline__ void fence_async() {
    asm volatile("fence.proxy.async.shared::cta;" ::: "memory");
}

__global__ __launch_bounds__(TPB, 3) void fused_kernel(
    const float* __restrict__ geo, const int* __restrict__ pos,
    const float* __restrict__ mgo, const int* __restrict__ gt,
    const float* __restrict__ aux, const float* __restrict__ tok,
    const float* __restrict__ sigma, float* __restrict__ out,
    int B, long nrows, long NTg, long NT, ContTab cont)
{
    // Per-warp private double-buffered slices, filled by cp.async.bulk (TMA-
    // class DMA engine) with per-warp-per-buffer mbarrier completion. No block
    // barriers in the main loop; 24 independent pipelines/SM.
    extern __shared__ char shm[];
    __shared__ double shred[WPB * 5];
    __shared__ alignas(8) unsigned long long mbar_s[WPB][NBUF];

    const int tid  = threadIdx.x;
    const int lane = tid & 31;
    const int w    = tid >> 5;
    const unsigned int slice =
        (unsigned int)__cvta_generic_to_shared(shm) + w * WSLICE;
    const unsigned int mb0 =
        (unsigned int)__cvta_generic_to_shared(&mbar_s[w][0]);
    const unsigned int mb1 = mb0 + 8;

    if (lane == 0) { mbar_init(mb0); mbar_init(mb1); }
    __syncthreads();
    fence_async();          // init visible to the async proxy before first bulk

    // Geo: lane l (l<24) owns row l of a 2-batch tile; j = l%12, batch = l/12.
    // Row stride 132 B -> smem bank of elem i for lane l is (l+i)%32: conflict-free.
    const int  jj    = (lane < 12) ? lane : lane - 12;
    const int  batch = (lane < 12) ? 0 : 1;
    const float cwj  = CW_C[jj];
    const float cwj1 = cwj + 1.0f;

    float accS = 0.f, accV = 0.f, accC = 0.f, accE = 0.f, accP = 0.f;

    // Fill tile u into buffer bufidx via one bulk copy (lane 0). Tail bytes
    // (<16, only a ragged last mask tile) copied synchronously by lanes.
    auto load_tile = [&](long u, int bufidx) {
        const unsigned int dst = slice + bufidx * WTILE;
        const unsigned int mb  = bufidx ? mb1 : mb0;
        const char* src;
        int bytes;
        if (u < NTg) {
            const long b0 = u * 2;
            const int  nb = (int)min(2L, (long)B - b0);
            src   = (const char*)(geo + b0 * 396);
            bytes = nb * 1584;                        // always % 16 == 0
        } else {
            const long r0 = (u - NTg) * 32;
            const int  nr = (int)min(32L, nrows - r0);
            src   = (const char*)(mgo + r0 * 33);
            bytes = nr * 132;
        }
        const unsigned int bb = (unsigned int)(bytes & ~15);   // bulk part
        fence_async();       // order prior generic smem reads before async write
        if (lane == 0) {
            mbar_expect_tx(mb, bb);
            bulk_g2s(dst, src, bb, mb);
        }
        const int tf = (bytes & 15) >> 2;             // 0..3 tail floats
        if (lane < tf) {
            float v = *(const float*)(src + bb + lane * 4);
            *(float*)(shm + (size_t)w * WSLICE + (size_t)bufidx * WTILE
                      + bb + lane * 4) = v;
        }
    };

    const long gw = (long)blockIdx.x * WPB + w;      // global warp id
    const long nw = (long)gridDim.x * WPB;           // total warps

    if (gw < NT) load_tile(gw, 0);

    int cur = 0;
    int ph0 = 0, ph1 = 0;                            // parity per buffer
    for (long u = gw; u < NT; u += nw) {
        const long un = u + nw;
        if (un < NT) load_tile(un, cur ^ 1);

        // Hoisted index/target loads for tile u (hide under the mbarrier wait).
        int  pre = -100;
        int  nb = 0, nr = 0;
        long b0 = 0, r0 = 0;
        if (u < NTg) {
            b0 = u * 2;
            nb = (int)min(2L, (long)B - b0);
            if (lane < nb * 12) pre = pos[(b0 + batch) * 13 + jj + 1];
        } else {
            r0 = (u - NTg) * 32;
            nr = (int)min(32L, nrows - r0);
            if (lane < nr) pre = gt[r0 + lane];
        }

        if (cur == 0) { mbar_wait(mb0, ph0); ph0 ^= 1; }
        else          { mbar_wait(mb1, ph1); ph1 ^= 1; }
        __syncwarp();                                // all lanes see the tile

        const float* buf = (const float*)(shm + (size_t)w * WSLICE
                                              + (size_t)cur * WTILE);
        if (u < NTg) {
            // ------------- geo tile: 2 batches x 12 positions -------------
            const bool act = lane < nb * 12;
            float cel = 0.f;
            bool  cor = false;
            if (act) {
                const float* p = buf + lane * 33;
                float m0 = -1e30f, m1 = -1e30f, m2 = -1e30f, m3 = -1e30f;
                float s0 = 0.f, s1 = 0.f, s2 = 0.f, s3 = 0.f;
                #pragma unroll
                for (int i = 0; i < 32; i += 4) {
                    float a = p[i], b = p[i+1], c = p[i+2], d = p[i+3];
                    m0 = fmaxf(m0, a); m1 = fmaxf(m1, b);
                    m2 = fmaxf(m2, c); m3 = fmaxf(m3, d);
                    s0 += __expf(a); s1 += __expf(b);
                    s2 += __expf(c); s3 += __expf(d);
                }
                const float e32 = p[32];
                const float m = fmaxf(fmaxf(fmaxf(m0, m1), fmaxf(m2, m3)), e32);
                const float s = (s0 + s1) + (s2 + s3) + __expf(e32);
                const float pt = p[pre];             // pre in 0..32 when act
                cor = (pt == m);       // ties measure-zero for random logits
                cel = (pre == 32) ? 0.f : (__logf(s) - pt);
            }
            const unsigned bal = __ballot_sync(FULLM, cor);
            if (act) {
                const unsigned m12 = (bal >> (batch * 12)) & 0xFFFu;
                const int mi = (m12 == 0xFFFu) ? 0 : (__ffs((int)~m12) - 1);
                const bool ok = (m12 >> jj) & 1u;
                accC += ok ? cel * cwj  : 0.f;
                accE += ok ? 0.f        : cel * cwj1;
                accP += (jj < mi) ? cel * cont.v[mi] : 0.f;
            }
        } else {
            // ------------- mask tile: 32 rows of 33 -------------
            if (lane < nr) {
                const float* p = buf + lane * 33;
                float s0 = 0.f, s1 = 0.f, s2 = 0.f, s3 = 0.f;
                #pragma unroll
                for (int i = 0; i < 32; i += 4) {
                    s0 += __expf(p[i]);   s1 += __expf(p[i+1]);
                    s2 += __expf(p[i+2]); s3 += __expf(p[i+3]);
                }
                const float s = (s0 + s1) + (s2 + s3) + __expf(p[32]);
                const int tc = min(max(pre, 0), 32);
                if (pre != -100) {
                    accS += __logf(s) - p[tc];
                    accV += 1.f;
                }
            }
        }
        __syncwarp();       // all lanes done reading buf before it is refilled
        cur ^= 1;
    }
    // Every issued bulk was awaited (prefetch only for tiles that get consumed).

    // ---------------- block reduction -> global atomics ----------------
    double d0 = warp_dsum((double)accS);
    double d1 = warp_dsum((double)accV);
    double d2 = warp_dsum((double)accC);
    double d3 = warp_dsum((double)accE);
    double d4 = warp_dsum((double)accP);
    if (lane == 0) {
        shred[w] = d0; shred[WPB + w] = d1; shred[2*WPB + w] = d2;
        shred[3*WPB + w] = d3; shred[4*WPB + w] = d4;
    }
    __syncthreads();
    if (tid == 0) {
        double a0 = 0, a1 = 0, a2 = 0, a3 = 0, a4 = 0;
        #pragma unroll
        for (int i = 0; i < WPB; i++) {
            a0 += shred[i];          a1 += shred[WPB + i];
            a2 += shred[2*WPB + i];  a3 += shred[3*WPB + i];
            a4 += shred[4*WPB + i];
        }
        atomicAdd(&g_acc[0], a0);
        atomicAdd(&g_acc[1], a1);
        atomicAdd(&g_acc[2], a2);
        atomicAdd(&g_acc[3], a3);
        atomicAdd(&g_acc[4], a4);
        __threadfence();
        unsigned done = atomicAdd(&g_done, 1u);
        if (done == gridDim.x - 1) {
            // last block: read-and-zero (deterministic across graph replays)
            double s0 = __longlong_as_double(atomicExch((unsigned long long*)&g_acc[0], 0ull));
            double s1 = __longlong_as_double(atomicExch((unsigned long long*)&g_acc[1], 0ull));
            double s2 = __longlong_as_double(atomicExch((unsigned long long*)&g_acc[2], 0ull));
            double s3 = __longlong_as_double(atomicExch((unsigned long long*)&g_acc[3], 0ull));
            double s4 = __longlong_as_double(atomicExch((unsigned long long*)&g_acc[4], 0ull));
            atomicExch(&g_done, 0u);

            const double den = (double)B * 12.0;
            double mask_loss = s0 / fmax(s1, 1.0);
            double pl = s4 / den, cl = s2 / den, el = s3 / den;
            double gl = pl + cl + el;
            double L[4] = { gl, mask_loss, (double)aux[0], (double)tok[0] };
            double wsum = 0.0, prod = 1.0;
            #pragma unroll
            for (int i = 0; i < 4; i++) {
                double sg = (double)sigma[i];
                wsum += 0.5 * L[i] / (sg * sg);
                prod *= sg;
            }
            wsum += log(prod);
            out[0] = (float)wsum;
            out[1] = (float)pl;
            out[2] = (float)cl;
            out[3] = (float)el;
            out[4] = (float)mask_loss;
        }
    }
}

extern "C" void kernel_launch(void* const* d_in, const int* in_sizes, int n_in,
                              void* d_out, int out_size) {
    (void)n_in; (void)out_size;
    const float* geo   = (const float*)d_in[0];   // (B, 12, 33) f32
    const float* mgo   = (const float*)d_in[1];   // (B, 13, 33) f32
    const int*   pos   = (const int*)  d_in[2];   // (B, 13) i32
    const int*   gt    = (const int*)  d_in[3];   // (B, 13) i32
    const float* aux   = (const float*)d_in[4];
    const float* tok   = (const float*)d_in[5];
    const float* sigma = (const float*)d_in[6];
    float* out = (float*)d_out;

    const int  B     = (int)((long)in_sizes[0] / 396);
    const long nrows = (long)in_sizes[1] / 33;    // B * 13
    const long NTg   = ((long)B + 1) / 2;         // geo tiles (2 batches each)
    const long NTm   = (nrows + 31) / 32;         // mask tiles (32 rows each)
    const long NT    = NTg + NTm;

    // CONT_REWARDS closed-form geometric series == reference's Riemann sum
    ContTab cont;
    cont.v[0] = 0.0f;
    for (int k = 1; k <= 12; k++) {
        double b = (double)k;
        double r = pow(0.8, b / 1999.0);
        double integral = (b / 2000.0) * (1.0 - pow(r, 2000.0)) / (1.0 - r);
        cont.v[k] = (float)(1.0 / integral);
    }

    const int dyn_smem = WPB * WSLICE;            // 8 warps * 8448 B = 67584 B
    cudaFuncSetAttribute(fused_kernel,
                         cudaFuncAttributeMaxDynamicSharedMemorySize, dyn_smem);
    fused_kernel<<<GRID, TPB, dyn_smem>>>(geo, pos, mgo, gt, aux, tok, sigma, out,
                                          B, nrows, NTg, NT, cont);
}